// round 7
// baseline (speedup 1.0000x reference)
#include <cuda_runtime.h>
#include <cuda_bf16.h>
#include <math.h>

#define Kk 32
#define Hh 480
#define Ww 480
#define Nn 576
#define Dd 1024
#define CLSD 64
#define OUTD 256
#define INDIM 1093
#define BK 256
#define XS 1096   // padded row stride of assembled x
#define NSPLIT 8
#define SLEN 137  // ceil(1093/8)

// ---- scratch (static device globals: allocation-free) ----
__device__ int      g_stat[BK][8];        // area, sx, sy, xmn, xmx, ymn, ymx
__device__ unsigned g_bits[BK * 18];      // 576-bit sample mask per (b,k)
__device__ int      g_cnt[BK];
__device__ float    g_x[BK * XS];         // assembled [pooled | cls | geom]
__device__ float    g_part[NSPLIT * BK * OUTD];

// ============================================================
// Kernel 0: init stats, sample bits, class-embedding gather.
// grid = 256 (one per b,k), 576 threads (24x24 sample grid).
// ============================================================
__global__ __launch_bounds__(576) void k_init(const int* __restrict__ masks,
                                              const void* __restrict__ cls_raw,
                                              const float* __restrict__ emb) {
    const int bk  = blockIdx.x;
    const int tid = threadIdx.x;
    const int wid = tid >> 5, lid = tid & 31;
    __shared__ int s_flag, s_cnt;
    if (tid == 0) { s_flag = 0; s_cnt = 0; }
    if (tid < 8) {
        int v = 0;
        if (tid == 3 || tid == 5) v = 1 << 29;   // xmn, ymn init BIG
        if (tid == 4 || tid == 6) v = -1;        // xmx, ymx init
        g_stat[bk][tid] = v;
    }
    __syncthreads();
    // detect int64 vs int32 class_ids (odd 32-bit words all zero => int64)
    if (tid < 128) {
        if (((const int*)cls_raw)[2 * tid + 1] != 0) atomicOr(&s_flag, 1);
    }
    // sampled 24x24 bits (nearest: src = 20*i, 20*j)
    const int* mb = masks + (size_t)bk * (Hh * Ww);
    int i = tid / 24, j = tid - i * 24;
    int on = mb[(20 * i) * Ww + 20 * j] > 0;
    unsigned bal = __ballot_sync(0xffffffffu, on);
    if (lid == 0) { g_bits[bk * 18 + wid] = bal; atomicAdd(&s_cnt, __popc(bal)); }
    __syncthreads();
    if (tid == 0) g_cnt[bk] = s_cnt;
    const bool is64 = (s_flag == 0);
    int c = is64 ? (int)((const long long*)cls_raw)[bk]
                 : ((const int*)cls_raw)[bk];
    if (tid < CLSD) g_x[(size_t)bk * XS + Dd + tid] = emb[c * CLSD + tid];
}

// ============================================================
// Kernel 1: full-res mask stats. Branch-free, division-free, fully unrolled
// => 30 front-batched LDG.128 per thread, DRAM-bound (~236 MB).
// grid = (4 row-chunks, 256 bk), 480 threads.
// ============================================================
__global__ __launch_bounds__(480) void k_mask(const int* __restrict__ masks) {
    const int chunk = blockIdx.x;          // 0..3 (120 rows each)
    const int bk    = blockIdx.y;
    const int tid   = threadIdx.x;
    const int col4  = tid % 120;
    const int rowg  = tid / 120;           // 0..3
    const int h0    = chunk * 120 + rowg;
    const int4* mp  = reinterpret_cast<const int4*>(masks + (size_t)bk * (Hh * Ww))
                      + (size_t)h0 * 120 + col4;

    int area = 0, itc = 0, sxo = 0, occ = 0;
    int ymni = 1000, ymxi = -1;
    #pragma unroll
    for (int it = 0; it < 30; it++) {
        int4 v = __ldg(&mp[(size_t)it * 480]);
        int c = v.x + v.y + v.z + v.w;
        area += c;
        itc  += c * it;
        sxo  += v.y + 2 * v.z + 3 * v.w;
        occ  |= v.x + 2 * v.y + 4 * v.z + 8 * v.w;
        ymni = min(ymni, c ? it : 1000);
        ymxi = max(ymxi, c ? it : -1);
    }
    const int w4 = col4 * 4;
    int sx = w4 * area + sxo;
    int sy = h0 * area + 4 * itc;
    int xmn = occ ? (w4 + __ffs(occ) - 1)  : (1 << 29);
    int xmx = occ ? (w4 + 31 - __clz(occ)) : -1;
    int ymn = (ymxi >= 0) ? (h0 + 4 * ymni) : (1 << 29);
    int ymx = (ymxi >= 0) ? (h0 + 4 * ymxi) : -1;

    #pragma unroll
    for (int off = 16; off; off >>= 1) {
        area += __shfl_down_sync(0xffffffffu, area, off);
        sx   += __shfl_down_sync(0xffffffffu, sx, off);
        sy   += __shfl_down_sync(0xffffffffu, sy, off);
        xmn = min(xmn, __shfl_down_sync(0xffffffffu, xmn, off));
        xmx = max(xmx, __shfl_down_sync(0xffffffffu, xmx, off));
        ymn = min(ymn, __shfl_down_sync(0xffffffffu, ymn, off));
        ymx = max(ymx, __shfl_down_sync(0xffffffffu, ymx, off));
    }
    __shared__ int sA[15], sX[15], sY[15], sxm[15], sxM[15], sym[15], syM[15];
    const int wid = tid >> 5, lid = tid & 31;
    if (lid == 0) {
        sA[wid] = area; sX[wid] = sx; sY[wid] = sy;
        sxm[wid] = xmn; sxM[wid] = xmx; sym[wid] = ymn; syM[wid] = ymx;
    }
    __syncthreads();
    if (tid == 0) {
        int A = 0, X = 0, Y = 0, xm = 1 << 29, xM = -1, ym = 1 << 29, yM = -1;
        #pragma unroll
        for (int i = 0; i < 15; i++) {
            A += sA[i]; X += sX[i]; Y += sY[i];
            xm = min(xm, sxm[i]); xM = max(xM, sxM[i]);
            ym = min(ym, sym[i]); yM = max(yM, syM[i]);
        }
        atomicAdd(&g_stat[bk][0], A);
        atomicAdd(&g_stat[bk][1], X);
        atomicAdd(&g_stat[bk][2], Y);
        atomicMin(&g_stat[bk][3], xm);
        atomicMax(&g_stat[bk][4], xM);
        atomicMin(&g_stat[bk][5], ym);
        atomicMax(&g_stat[bk][6], yM);
    }
}

// ============================================================
// Kernel 2: masked pooling, direct streaming LDG + 0/1 FFMA multipliers.
// grid = (4 d-chunks, 4 k-groups of 8, 8 b) = 128 blocks, 256 thr.
// fm is L2-resident after first k-group; no phase barriers in mainloop.
// Also finalizes geometry into g_x.
// ============================================================
__global__ __launch_bounds__(256) void k_pool(const float* __restrict__ fm) {
    const int dc  = blockIdx.x;   // 0..3
    const int kg  = blockIdx.y;   // 0..3
    const int b   = blockIdx.z;   // 0..7
    const int tid = threadIdx.x;
    const int d   = dc * 256 + tid;
    const int k0  = kg * 8;

    __shared__ alignas(16) float4 s_m[Nn][2];
    __shared__ float s_inv[8];

    if (dc == 0 && kg == 0 && tid < Kk) {
        const int bk = b * Kk + tid;
        int A = g_stat[bk][0], SX = g_stat[bk][1], SY = g_stat[bk][2];
        int xm = g_stat[bk][3], xM = g_stat[bk][4];
        int ym = g_stat[bk][5], yM = g_stat[bk][6];
        float af = (float)A, safe = fmaxf(af, 1.0f);
        bool valid = (A >= 1);
        float* gx = g_x + (size_t)bk * XS + Dd + CLSD;
        gx[0] = valid ? (float)SX / safe * (1.0f / Ww) : 0.0f;
        gx[1] = valid ? (float)SY / safe * (1.0f / Hh) : 0.0f;
        gx[2] = valid ? af * (1.0f / (Hh * Ww)) : 0.0f;
        gx[3] = valid ? (float)(xM - xm + 1) * (1.0f / Ww) : 0.0f;
        gx[4] = valid ? (float)(yM - ym + 1) * (1.0f / Hh) : 0.0f;
    }

    for (int n = tid; n < Nn; n += 256) {
        float mk[8];
        #pragma unroll
        for (int kk = 0; kk < 8; kk++) {
            unsigned word = g_bits[(b * Kk + k0 + kk) * 18 + (n >> 5)];
            mk[kk] = ((word >> (n & 31)) & 1u) ? 1.0f : 0.0f;
        }
        s_m[n][0] = make_float4(mk[0], mk[1], mk[2], mk[3]);
        s_m[n][1] = make_float4(mk[4], mk[5], mk[6], mk[7]);
    }
    if (tid < 8) {
        int c = g_cnt[b * Kk + k0 + tid];
        s_inv[tid] = (c > 0) ? (1.0f / (float)c) : 0.0f;
    }
    __syncthreads();

    const float* fp = fm + (size_t)b * Nn * Dd + d;
    float a0 = 0.f, a1 = 0.f, a2 = 0.f, a3 = 0.f;
    float a4 = 0.f, a5 = 0.f, a6 = 0.f, a7 = 0.f;

    #pragma unroll 8
    for (int n = 0; n < Nn; n++) {
        float f = __ldg(fp + (size_t)n * Dd);
        float4 m0 = s_m[n][0];
        float4 m1 = s_m[n][1];
        a0 = fmaf(f, m0.x, a0); a1 = fmaf(f, m0.y, a1);
        a2 = fmaf(f, m0.z, a2); a3 = fmaf(f, m0.w, a3);
        a4 = fmaf(f, m1.x, a4); a5 = fmaf(f, m1.y, a5);
        a6 = fmaf(f, m1.z, a6); a7 = fmaf(f, m1.w, a7);
    }

    float* pp = g_x + (size_t)(b * Kk + k0) * XS + d;
    pp[0 * XS] = a0 * s_inv[0];
    pp[1 * XS] = a1 * s_inv[1];
    pp[2 * XS] = a2 * s_inv[2];
    pp[3 * XS] = a3 * s_inv[3];
    pp[4 * XS] = a4 * s_inv[4];
    pp[5 * XS] = a5 * s_inv[5];
    pp[6 * XS] = a6 * s_inv[6];
    pp[7 * XS] = a7 * s_inv[7];
}

// ============================================================
// Kernel 3a: layer1 partial GEMM, 8-way split-i, direct W1 loads.
// grid = (8 splits, 32 row-groups of 8) = 256 blocks, 256 threads.
// Per block: 8 rows x 256 cols x K<=137. W1 tile read coalesced from L2.
// ============================================================
__global__ __launch_bounds__(256) void k_mlp1(const float* __restrict__ W1) {
    const int split = blockIdx.x;            // 0..7
    const int rg    = blockIdx.y;            // rows rg*8..rg*8+7
    const int j     = threadIdx.x;
    const int i0    = split * SLEN;
    const int len   = min(SLEN, INDIM - i0); // 137 or 134

    __shared__ alignas(16) float xs[8][SLEN + 3];

    #pragma unroll
    for (int r = 0; r < 8; r++) {
        if (j < len) xs[r][j] = g_x[(size_t)(rg * 8 + r) * XS + i0 + j];
    }
    __syncthreads();

    const float* wp = W1 + (size_t)i0 * OUTD + j;
    float a[8];
    #pragma unroll
    for (int r = 0; r < 8; r++) a[r] = 0.f;

    int t = 0;
    #pragma unroll 2
    for (; t + 8 <= len; t += 8) {
        float w0 = wp[(size_t)(t + 0) * OUTD];
        float w1 = wp[(size_t)(t + 1) * OUTD];
        float w2 = wp[(size_t)(t + 2) * OUTD];
        float w3 = wp[(size_t)(t + 3) * OUTD];
        float w4 = wp[(size_t)(t + 4) * OUTD];
        float w5 = wp[(size_t)(t + 5) * OUTD];
        float w6 = wp[(size_t)(t + 6) * OUTD];
        float w7 = wp[(size_t)(t + 7) * OUTD];
        #pragma unroll
        for (int r = 0; r < 8; r++) {
            float4 xa = *(const float4*)&xs[r][t];
            float4 xb = *(const float4*)&xs[r][t + 4];
            a[r] = fmaf(xa.x, w0, a[r]); a[r] = fmaf(xa.y, w1, a[r]);
            a[r] = fmaf(xa.z, w2, a[r]); a[r] = fmaf(xa.w, w3, a[r]);
            a[r] = fmaf(xb.x, w4, a[r]); a[r] = fmaf(xb.y, w5, a[r]);
            a[r] = fmaf(xb.z, w6, a[r]); a[r] = fmaf(xb.w, w7, a[r]);
        }
    }
    for (; t < len; t++) {
        float w = wp[(size_t)t * OUTD];
        #pragma unroll
        for (int r = 0; r < 8; r++) a[r] = fmaf(xs[r][t], w, a[r]);
    }

    float* gp = g_part + (size_t)(split * BK + rg * 8) * OUTD + j;
    #pragma unroll
    for (int r = 0; r < 8; r++) gp[(size_t)r * OUTD] = a[r];
}

// ============================================================
// Kernel 3b: combine 8 partials + bias + exact GELU + LayerNorm + layer2.
// grid = 256 blocks (1 row each), 256 threads, direct W2 loads.
// ============================================================
__global__ __launch_bounds__(256) void k_mlp2(const float* __restrict__ b1,
                                              const float* __restrict__ ln_g,
                                              const float* __restrict__ ln_b,
                                              const float* __restrict__ W2,
                                              const float* __restrict__ b2,
                                              float* __restrict__ out) {
    const int row = blockIdx.x;
    const int j   = threadIdx.x;

    __shared__ alignas(16) float hn[OUTD];
    __shared__ float red[2][8];
    __shared__ float mu_s, is_s;

    float v = b1[j];
    #pragma unroll
    for (int s = 0; s < NSPLIT; s++)
        v += g_part[(size_t)(s * BK + row) * OUTD + j];
    v = 0.5f * v * (1.0f + erff(v * 0.7071067811865476f));

    float s1 = v, s2 = v * v;
    #pragma unroll
    for (int off = 16; off; off >>= 1) {
        s1 += __shfl_down_sync(0xffffffffu, s1, off);
        s2 += __shfl_down_sync(0xffffffffu, s2, off);
    }
    if ((j & 31) == 0) { red[0][j >> 5] = s1; red[1][j >> 5] = s2; }
    __syncthreads();
    if (j == 0) {
        float a = 0.f, b = 0.f;
        #pragma unroll
        for (int w = 0; w < 8; w++) { a += red[0][w]; b += red[1][w]; }
        float mu  = a * (1.0f / OUTD);
        float var = b * (1.0f / OUTD) - mu * mu;
        mu_s = mu;
        is_s = rsqrtf(var + 1e-5f);
    }
    __syncthreads();
    hn[j] = (v - mu_s) * is_s * ln_g[j] + ln_b[j];
    __syncthreads();

    const float* wp = W2 + j;
    float o = b2[j];
    #pragma unroll 4
    for (int i = 0; i < OUTD; i += 8) {
        float w0 = wp[(size_t)(i + 0) * OUTD];
        float w1 = wp[(size_t)(i + 1) * OUTD];
        float w2 = wp[(size_t)(i + 2) * OUTD];
        float w3 = wp[(size_t)(i + 3) * OUTD];
        float w4 = wp[(size_t)(i + 4) * OUTD];
        float w5 = wp[(size_t)(i + 5) * OUTD];
        float w6 = wp[(size_t)(i + 6) * OUTD];
        float w7 = wp[(size_t)(i + 7) * OUTD];
        float4 ha = *(const float4*)&hn[i];
        float4 hb = *(const float4*)&hn[i + 4];
        o = fmaf(ha.x, w0, o); o = fmaf(ha.y, w1, o);
        o = fmaf(ha.z, w2, o); o = fmaf(ha.w, w3, o);
        o = fmaf(hb.x, w4, o); o = fmaf(hb.y, w5, o);
        o = fmaf(hb.z, w6, o); o = fmaf(hb.w, w7, o);
    }
    out[(size_t)row * OUTD + j] = o;
}

// ============================================================
extern "C" void kernel_launch(void* const* d_in, const int* in_sizes, int n_in,
                              void* d_out, int out_size) {
    const float* fm    = (const float*)d_in[0];
    const int*   masks = (const int*)d_in[1];
    const void*  cls   = d_in[2];
    const float* emb   = (const float*)d_in[3];
    const float* W1    = (const float*)d_in[4];
    const float* b1    = (const float*)d_in[5];
    const float* lg    = (const float*)d_in[6];
    const float* lb    = (const float*)d_in[7];
    const float* W2    = (const float*)d_in[8];
    const float* b2    = (const float*)d_in[9];
    float* out = (float*)d_out;

    k_init<<<BK, 576>>>(masks, cls, emb);
    k_mask<<<dim3(4, BK), 480>>>(masks);
    k_pool<<<dim3(4, 4, 8), 256>>>(fm);
    k_mlp1<<<dim3(NSPLIT, 32), 256>>>(W1);
    k_mlp2<<<BK, 256>>>(b1, lg, lb, W2, b2, out);
}

// round 8
// speedup vs baseline: 1.2650x; 1.2650x over previous
#include <cuda_runtime.h>
#include <cuda_bf16.h>
#include <math.h>

#define Kk 32
#define Hh 480
#define Ww 480
#define Nn 576
#define Dd 1024
#define CLSD 64
#define OUTD 256
#define INDIM 1093
#define BK 256
#define XS 1096   // padded row stride of assembled x
#define NSPLIT 8
#define SLEN 137  // ceil(1093/8)

// ---- scratch (static device globals: allocation-free) ----
__device__ int      g_stat4[4][BK][8];    // per-chunk partial stats (no init needed)
__device__ unsigned g_bits[BK * 18];      // 576-bit sample mask per (b,k)
__device__ int      g_cnt[BK];
__device__ float    g_x[BK * XS];         // assembled [pooled | cls | (geom inline)]
__device__ float    g_part[NSPLIT * BK * OUTD];

// ============================================================
// Kernel 0: sample bits + class-embedding gather.
// grid = 256 (one per b,k), 576 threads (24x24 sample grid).
// ============================================================
__global__ __launch_bounds__(576) void k_init(const int* __restrict__ masks,
                                              const void* __restrict__ cls_raw,
                                              const float* __restrict__ emb) {
    const int bk  = blockIdx.x;
    const int tid = threadIdx.x;
    const int wid = tid >> 5, lid = tid & 31;
    __shared__ int s_flag, s_cnt;
    if (tid == 0) { s_flag = 0; s_cnt = 0; }
    __syncthreads();
    // detect int64 vs int32 class_ids (odd 32-bit words all zero => int64)
    if (tid < 128) {
        if (((const int*)cls_raw)[2 * tid + 1] != 0) atomicOr(&s_flag, 1);
    }
    // sampled 24x24 bits (nearest: src = 20*i, 20*j)
    const int* mb = masks + (size_t)bk * (Hh * Ww);
    int i = tid / 24, j = tid - i * 24;
    int on = mb[(20 * i) * Ww + 20 * j] > 0;
    unsigned bal = __ballot_sync(0xffffffffu, on);
    if (lid == 0) { g_bits[bk * 18 + wid] = bal; atomicAdd(&s_cnt, __popc(bal)); }
    __syncthreads();
    if (tid == 0) g_cnt[bk] = s_cnt;
    const bool is64 = (s_flag == 0);
    int c = is64 ? (int)((const long long*)cls_raw)[bk]
                 : ((const int*)cls_raw)[bk];
    if (tid < CLSD) g_x[(size_t)bk * XS + Dd + tid] = emb[c * CLSD + tid];
}

// ============================================================
// Kernel 1: full-res mask stats. Branch/division-free, 30 front-batched
// LDG.128 per thread, DRAM-bound (~236 MB). Writes per-chunk slot (no atomics,
// no init dependency) -> runs fully independent on its own stream.
// grid = (4 row-chunks, 256 bk), 480 threads.
// ============================================================
__global__ __launch_bounds__(480) void k_mask(const int* __restrict__ masks) {
    const int chunk = blockIdx.x;          // 0..3 (120 rows each)
    const int bk    = blockIdx.y;
    const int tid   = threadIdx.x;
    const int col4  = tid % 120;
    const int rowg  = tid / 120;           // 0..3
    const int h0    = chunk * 120 + rowg;
    const int4* mp  = reinterpret_cast<const int4*>(masks + (size_t)bk * (Hh * Ww))
                      + (size_t)h0 * 120 + col4;

    int area = 0, itc = 0, sxo = 0, occ = 0;
    int ymni = 1000, ymxi = -1;
    #pragma unroll
    for (int it = 0; it < 30; it++) {
        int4 v = __ldg(&mp[(size_t)it * 480]);
        int c = v.x + v.y + v.z + v.w;
        area += c;
        itc  += c * it;
        sxo  += v.y + 2 * v.z + 3 * v.w;
        occ  |= v.x + 2 * v.y + 4 * v.z + 8 * v.w;
        ymni = min(ymni, c ? it : 1000);
        ymxi = max(ymxi, c ? it : -1);
    }
    const int w4 = col4 * 4;
    int sx = w4 * area + sxo;
    int sy = h0 * area + 4 * itc;
    int xmn = occ ? (w4 + __ffs(occ) - 1)  : (1 << 29);
    int xmx = occ ? (w4 + 31 - __clz(occ)) : -1;
    int ymn = (ymxi >= 0) ? (h0 + 4 * ymni) : (1 << 29);
    int ymx = (ymxi >= 0) ? (h0 + 4 * ymxi) : -1;

    #pragma unroll
    for (int off = 16; off; off >>= 1) {
        area += __shfl_down_sync(0xffffffffu, area, off);
        sx   += __shfl_down_sync(0xffffffffu, sx, off);
        sy   += __shfl_down_sync(0xffffffffu, sy, off);
        xmn = min(xmn, __shfl_down_sync(0xffffffffu, xmn, off));
        xmx = max(xmx, __shfl_down_sync(0xffffffffu, xmx, off));
        ymn = min(ymn, __shfl_down_sync(0xffffffffu, ymn, off));
        ymx = max(ymx, __shfl_down_sync(0xffffffffu, ymx, off));
    }
    __shared__ int sA[15], sX[15], sY[15], sxm[15], sxM[15], sym[15], syM[15];
    const int wid = tid >> 5, lid = tid & 31;
    if (lid == 0) {
        sA[wid] = area; sX[wid] = sx; sY[wid] = sy;
        sxm[wid] = xmn; sxM[wid] = xmx; sym[wid] = ymn; syM[wid] = ymx;
    }
    __syncthreads();
    if (tid == 0) {
        int A = 0, X = 0, Y = 0, xm = 1 << 29, xM = -1, ym = 1 << 29, yM = -1;
        #pragma unroll
        for (int i = 0; i < 15; i++) {
            A += sA[i]; X += sX[i]; Y += sY[i];
            xm = min(xm, sxm[i]); xM = max(xM, sxM[i]);
            ym = min(ym, sym[i]); yM = max(yM, syM[i]);
        }
        int* st = g_stat4[chunk][bk];
        st[0] = A; st[1] = X; st[2] = Y;
        st[3] = xm; st[4] = xM; st[5] = ym; st[6] = yM;
    }
}

// ============================================================
// Kernel 2: masked pooling via SMEM-staged fm tiles + 0/1 multipliers.
// grid = (4 d-chunks, 4 k-groups of 8, 8 b), 256 threads. (R6 version)
// ============================================================
__global__ __launch_bounds__(256) void k_pool(const float* __restrict__ fm) {
    const int dc  = blockIdx.x;   // 0..3
    const int kg  = blockIdx.y;   // 0..3
    const int b   = blockIdx.z;   // 0..7
    const int tid = threadIdx.x;
    const int d   = dc * 256 + tid;
    const int k0  = kg * 8;

    __shared__ alignas(16) float4 s_m[Nn][2];      // 18.4 KB
    __shared__ alignas(16) float  s_f[24][256];    // 24 KB
    __shared__ float s_inv[8];

    for (int n = tid; n < Nn; n += 256) {
        float mk[8];
        #pragma unroll
        for (int kk = 0; kk < 8; kk++) {
            unsigned word = g_bits[(b * Kk + k0 + kk) * 18 + (n >> 5)];
            mk[kk] = ((word >> (n & 31)) & 1u) ? 1.0f : 0.0f;
        }
        s_m[n][0] = make_float4(mk[0], mk[1], mk[2], mk[3]);
        s_m[n][1] = make_float4(mk[4], mk[5], mk[6], mk[7]);
    }
    if (tid < 8) {
        int c = g_cnt[b * Kk + k0 + tid];
        s_inv[tid] = (c > 0) ? (1.0f / (float)c) : 0.0f;
    }
    __syncthreads();

    float a0 = 0.f, a1 = 0.f, a2 = 0.f, a3 = 0.f;
    float a4 = 0.f, a5 = 0.f, a6 = 0.f, a7 = 0.f;
    const float* fb = fm + (size_t)b * Nn * Dd;
    const int r4 = tid >> 6, c4 = tid & 63;

    for (int n0 = 0; n0 < Nn; n0 += 24) {
        const float4* src = reinterpret_cast<const float4*>(fb + (size_t)n0 * Dd) + dc * 64;
        float4* dst = reinterpret_cast<float4*>(s_f);
        #pragma unroll
        for (int p = 0; p < 6; p++) {
            int r = r4 + p * 4;
            dst[r * 64 + c4] = src[(size_t)r * 256 + c4];
        }
        __syncthreads();
        #pragma unroll 8
        for (int r2 = 0; r2 < 24; r2++) {
            float f = s_f[r2][tid];
            float4 m0 = s_m[n0 + r2][0];
            float4 m1 = s_m[n0 + r2][1];
            a0 = fmaf(f, m0.x, a0); a1 = fmaf(f, m0.y, a1);
            a2 = fmaf(f, m0.z, a2); a3 = fmaf(f, m0.w, a3);
            a4 = fmaf(f, m1.x, a4); a5 = fmaf(f, m1.y, a5);
            a6 = fmaf(f, m1.z, a6); a7 = fmaf(f, m1.w, a7);
        }
        __syncthreads();
    }

    float* pp = g_x + (size_t)(b * Kk + k0) * XS + d;
    pp[0 * XS] = a0 * s_inv[0];
    pp[1 * XS] = a1 * s_inv[1];
    pp[2 * XS] = a2 * s_inv[2];
    pp[3 * XS] = a3 * s_inv[3];
    pp[4 * XS] = a4 * s_inv[4];
    pp[5 * XS] = a5 * s_inv[5];
    pp[6 * XS] = a6 * s_inv[6];
    pp[7 * XS] = a7 * s_inv[7];
}

// ============================================================
// Kernel 3a: layer1 partial GEMM, 8-way split-i, software-pipelined W1 loads.
// grid = (8 splits, 32 row-groups of 8) = 256 blocks, 256 threads.
// Split 7 computes geometry features inline from g_stat4 (no extra kernel).
// ============================================================
__global__ __launch_bounds__(256) void k_mlp1(const float* __restrict__ W1) {
    const int split = blockIdx.x;            // 0..7
    const int rg    = blockIdx.y;            // rows rg*8..rg*8+7
    const int j     = threadIdx.x;
    const int i0    = split * SLEN;
    const int len   = min(SLEN, INDIM - i0); // 137 or 134

    __shared__ alignas(16) float xs[8][SLEN + 3];

    const int lim = (split == 7) ? 129 : len;   // geom slots (129..133) computed inline
    #pragma unroll
    for (int r = 0; r < 8; r++) {
        if (j < lim) xs[r][j] = g_x[(size_t)(rg * 8 + r) * XS + i0 + j];
    }
    if (split == 7 && j < 40) {
        const int r = j / 5, gsel = j - r * 5;
        const int bk = rg * 8 + r;
        int A = 0, SX = 0, SY = 0, xm = 1 << 29, xM = -1, ym = 1 << 29, yM = -1;
        #pragma unroll
        for (int c = 0; c < 4; c++) {
            const int* st = g_stat4[c][bk];
            A += st[0]; SX += st[1]; SY += st[2];
            xm = min(xm, st[3]); xM = max(xM, st[4]);
            ym = min(ym, st[5]); yM = max(yM, st[6]);
        }
        float af = (float)A, safe = fmaxf(af, 1.0f);
        float val;
        if      (gsel == 0) val = (float)SX / safe * (1.0f / Ww);
        else if (gsel == 1) val = (float)SY / safe * (1.0f / Hh);
        else if (gsel == 2) val = af * (1.0f / (Hh * Ww));
        else if (gsel == 3) val = (float)(xM - xm + 1) * (1.0f / Ww);
        else                val = (float)(yM - ym + 1) * (1.0f / Hh);
        xs[r][129 + gsel] = (A >= 1) ? val : 0.0f;
    }
    __syncthreads();

    const float* wp = W1 + (size_t)i0 * OUTD + j;
    float a[8];
    #pragma unroll
    for (int r = 0; r < 8; r++) a[r] = 0.f;

    // software-pipelined: prefetch next 8 weight rows while FMA-ing current 8
    float w[8];
    #pragma unroll
    for (int u = 0; u < 8; u++) w[u] = wp[(size_t)u * OUTD];
    int t = 0;
    for (; t + 16 <= len; t += 8) {
        float wn[8];
        #pragma unroll
        for (int u = 0; u < 8; u++) wn[u] = wp[(size_t)(t + 8 + u) * OUTD];
        #pragma unroll
        for (int r = 0; r < 8; r++) {
            float4 xa = *(const float4*)&xs[r][t];
            float4 xb = *(const float4*)&xs[r][t + 4];
            a[r] = fmaf(xa.x, w[0], a[r]); a[r] = fmaf(xa.y, w[1], a[r]);
            a[r] = fmaf(xa.z, w[2], a[r]); a[r] = fmaf(xa.w, w[3], a[r]);
            a[r] = fmaf(xb.x, w[4], a[r]); a[r] = fmaf(xb.y, w[5], a[r]);
            a[r] = fmaf(xb.z, w[6], a[r]); a[r] = fmaf(xb.w, w[7], a[r]);
        }
        #pragma unroll
        for (int u = 0; u < 8; u++) w[u] = wn[u];
    }
    if (t + 8 <= len) {
        #pragma unroll
        for (int r = 0; r < 8; r++) {
            float4 xa = *(const float4*)&xs[r][t];
            float4 xb = *(const float4*)&xs[r][t + 4];
            a[r] = fmaf(xa.x, w[0], a[r]); a[r] = fmaf(xa.y, w[1], a[r]);
            a[r] = fmaf(xa.z, w[2], a[r]); a[r] = fmaf(xa.w, w[3], a[r]);
            a[r] = fmaf(xb.x, w[4], a[r]); a[r] = fmaf(xb.y, w[5], a[r]);
            a[r] = fmaf(xb.z, w[6], a[r]); a[r] = fmaf(xb.w, w[7], a[r]);
        }
        t += 8;
    }
    for (; t < len; t++) {
        float ws = wp[(size_t)t * OUTD];
        #pragma unroll
        for (int r = 0; r < 8; r++) a[r] = fmaf(xs[r][t], ws, a[r]);
    }

    float* gp = g_part + (size_t)(split * BK + rg * 8) * OUTD + j;
    #pragma unroll
    for (int r = 0; r < 8; r++) gp[(size_t)r * OUTD] = a[r];
}

// ============================================================
// Kernel 3b: combine 8 partials + bias + exact GELU + LayerNorm + layer2.
// grid = 256 blocks (1 row), 256 threads, software-pipelined W2 loads.
// ============================================================
__global__ __launch_bounds__(256) void k_mlp2(const float* __restrict__ b1,
                                              const float* __restrict__ ln_g,
                                              const float* __restrict__ ln_b,
                                              const float* __restrict__ W2,
                                              const float* __restrict__ b2,
                                              float* __restrict__ out) {
    const int row = blockIdx.x;
    const int j   = threadIdx.x;

    __shared__ alignas(16) float hn[OUTD];
    __shared__ float red[2][8];
    __shared__ float mu_s, is_s;

    float v = b1[j];
    #pragma unroll
    for (int s = 0; s < NSPLIT; s++)
        v += g_part[(size_t)(s * BK + row) * OUTD + j];
    v = 0.5f * v * (1.0f + erff(v * 0.7071067811865476f));

    float s1 = v, s2 = v * v;
    #pragma unroll
    for (int off = 16; off; off >>= 1) {
        s1 += __shfl_down_sync(0xffffffffu, s1, off);
        s2 += __shfl_down_sync(0xffffffffu, s2, off);
    }
    if ((j & 31) == 0) { red[0][j >> 5] = s1; red[1][j >> 5] = s2; }
    __syncthreads();
    if (j == 0) {
        float a = 0.f, b = 0.f;
        #pragma unroll
        for (int w = 0; w < 8; w++) { a += red[0][w]; b += red[1][w]; }
        float mu  = a * (1.0f / OUTD);
        float var = b * (1.0f / OUTD) - mu * mu;
        mu_s = mu;
        is_s = rsqrtf(var + 1e-5f);
    }
    __syncthreads();
    hn[j] = (v - mu_s) * is_s * ln_g[j] + ln_b[j];
    __syncthreads();

    const float* wp = W2 + j;
    float o = b2[j];
    float w[8];
    #pragma unroll
    for (int u = 0; u < 8; u++) w[u] = wp[(size_t)u * OUTD];
    int t = 0;
    for (; t + 16 <= OUTD; t += 8) {
        float wn[8];
        #pragma unroll
        for (int u = 0; u < 8; u++) wn[u] = wp[(size_t)(t + 8 + u) * OUTD];
        float4 ha = *(const float4*)&hn[t];
        float4 hb = *(const float4*)&hn[t + 4];
        o = fmaf(ha.x, w[0], o); o = fmaf(ha.y, w[1], o);
        o = fmaf(ha.z, w[2], o); o = fmaf(ha.w, w[3], o);
        o = fmaf(hb.x, w[4], o); o = fmaf(hb.y, w[5], o);
        o = fmaf(hb.z, w[6], o); o = fmaf(hb.w, w[7], o);
        #pragma unroll
        for (int u = 0; u < 8; u++) w[u] = wn[u];
    }
    {
        float4 ha = *(const float4*)&hn[t];
        float4 hb = *(const float4*)&hn[t + 4];
        o = fmaf(ha.x, w[0], o); o = fmaf(ha.y, w[1], o);
        o = fmaf(ha.z, w[2], o); o = fmaf(ha.w, w[3], o);
        o = fmaf(hb.x, w[4], o); o = fmaf(hb.y, w[5], o);
        o = fmaf(hb.z, w[6], o); o = fmaf(hb.w, w[7], o);
    }
    out[(size_t)row * OUTD + j] = o;
}

// ============================================================
extern "C" void kernel_launch(void* const* d_in, const int* in_sizes, int n_in,
                              void* d_out, int out_size) {
    const float* fm    = (const float*)d_in[0];
    const int*   masks = (const int*)d_in[1];
    const void*  cls   = d_in[2];
    const float* emb   = (const float*)d_in[3];
    const float* W1    = (const float*)d_in[4];
    const float* b1    = (const float*)d_in[5];
    const float* lg    = (const float*)d_in[6];
    const float* lb    = (const float*)d_in[7];
    const float* W2    = (const float*)d_in[8];
    const float* b2    = (const float*)d_in[9];
    float* out = (float*)d_out;

    // Fork-join: k_mask (DRAM-bound, independent) overlaps k_init+k_pool.
    cudaStream_t s1 = 0;
    cudaEvent_t  e0 = 0, e1 = 0;
    bool forked =
        (cudaStreamCreateWithFlags(&s1, cudaStreamNonBlocking) == cudaSuccess) &&
        (cudaEventCreateWithFlags(&e0, cudaEventDisableTiming) == cudaSuccess) &&
        (cudaEventCreateWithFlags(&e1, cudaEventDisableTiming) == cudaSuccess);

    if (forked) {
        cudaEventRecord(e0, 0);              // fork point on capture stream
        cudaStreamWaitEvent(s1, e0, 0);
        k_mask<<<dim3(4, BK), 480, 0, s1>>>(masks);
        cudaEventRecord(e1, s1);

        k_init<<<BK, 576>>>(masks, cls, emb);
        k_pool<<<dim3(4, 4, 8), 256>>>(fm);

        cudaStreamWaitEvent(0, e1, 0);       // join before geometry consumer
        k_mlp1<<<dim3(NSPLIT, 32), 256>>>(W1);
        k_mlp2<<<BK, 256>>>(b1, lg, lb, W2, b2, out);
    } else {
        k_init<<<BK, 576>>>(masks, cls, emb);
        k_mask<<<dim3(4, BK), 480>>>(masks);
        k_pool<<<dim3(4, 4, 8), 256>>>(fm);
        k_mlp1<<<dim3(NSPLIT, 32), 256>>>(W1);
        k_mlp2<<<BK, 256>>>(b1, lg, lb, W2, b2, out);
    }

    if (e0) cudaEventDestroy(e0);
    if (e1) cudaEventDestroy(e1);
    if (s1) cudaStreamDestroy(s1);
}

// round 9
// speedup vs baseline: 1.2784x; 1.0106x over previous
#include <cuda_runtime.h>
#include <cuda_bf16.h>
#include <math.h>

#define Kk 32
#define Hh 480
#define Ww 480
#define Nn 576
#define Dd 1024
#define CLSD 64
#define OUTD 256
#define INDIM 1093
#define BK 256
#define XS 1096    // padded row stride of assembled x
#define NSPLIT 16
#define SLEN 69    // ceil(1093/16)
#define GEOM_I 1088  // Dd + CLSD

// ---- scratch (static device globals: allocation-free) ----
__device__ int      g_stat4[4][BK][8];    // per-chunk partial stats (no init needed)
__device__ unsigned g_bits[BK * 18];      // 576-bit sample mask per (b,k)
__device__ int      g_cnt[BK];
__device__ float    g_x[BK * XS];         // assembled [pooled | cls | (geom inline)]
__device__ float    g_part[NSPLIT * BK * OUTD];

// ============================================================
// Kernel 0: sample bits + class-embedding gather.
// grid = 256 (one per b,k), 576 threads (24x24 sample grid).
// ============================================================
__global__ __launch_bounds__(576) void k_init(const int* __restrict__ masks,
                                              const void* __restrict__ cls_raw,
                                              const float* __restrict__ emb) {
    const int bk  = blockIdx.x;
    const int tid = threadIdx.x;
    const int wid = tid >> 5, lid = tid & 31;
    __shared__ int s_flag, s_cnt;
    if (tid == 0) { s_flag = 0; s_cnt = 0; }
    __syncthreads();
    // detect int64 vs int32 class_ids (odd 32-bit words all zero => int64)
    if (tid < 128) {
        if (((const int*)cls_raw)[2 * tid + 1] != 0) atomicOr(&s_flag, 1);
    }
    // sampled 24x24 bits (nearest: src = 20*i, 20*j)
    const int* mb = masks + (size_t)bk * (Hh * Ww);
    int i = tid / 24, j = tid - i * 24;
    int on = mb[(20 * i) * Ww + 20 * j] > 0;
    unsigned bal = __ballot_sync(0xffffffffu, on);
    if (lid == 0) { g_bits[bk * 18 + wid] = bal; atomicAdd(&s_cnt, __popc(bal)); }
    __syncthreads();
    if (tid == 0) g_cnt[bk] = s_cnt;
    const bool is64 = (s_flag == 0);
    int c = is64 ? (int)((const long long*)cls_raw)[bk]
                 : ((const int*)cls_raw)[bk];
    if (tid < CLSD) g_x[(size_t)bk * XS + Dd + tid] = emb[c * CLSD + tid];
}

// ============================================================
// Kernel 1: full-res mask stats. Explicit 10-deep load batches (pure LDG
// groups -> high MLP), pure-ALU processing, row bbox via occupancy bitmask.
// grid = (4 row-chunks, 256 bk), 480 threads. Target: DRAM roofline.
// ============================================================
__global__ __launch_bounds__(480) void k_mask(const int* __restrict__ masks) {
    const int chunk = blockIdx.x;          // 0..3 (120 rows each)
    const int bk    = blockIdx.y;
    const int tid   = threadIdx.x;
    const int col4  = tid % 120;
    const int rowg  = tid / 120;           // 0..3
    const int h0    = chunk * 120 + rowg;
    const int4* mp  = reinterpret_cast<const int4*>(masks + (size_t)bk * (Hh * Ww))
                      + (size_t)h0 * 120 + col4;

    int area = 0, itc = 0, sxo = 0, occ = 0;
    unsigned rocc = 0;
    #pragma unroll
    for (int g = 0; g < 3; g++) {
        int4 v[10];
        #pragma unroll
        for (int p = 0; p < 10; p++)
            v[p] = __ldg(&mp[(size_t)(g * 10 + p) * 480]);
        #pragma unroll
        for (int p = 0; p < 10; p++) {
            const int it = g * 10 + p;
            int c = v[p].x + v[p].y + v[p].z + v[p].w;
            area += c;
            itc  += c * it;
            sxo  += v[p].y + 2 * v[p].z + 3 * v[p].w;
            occ  |= v[p].x + 2 * v[p].y + 4 * v[p].z + 8 * v[p].w;
            rocc |= ((unsigned)(c + 3) >> 2) << it;     // 1 iff c>=1
        }
    }
    const int w4 = col4 * 4;
    int sx = w4 * area + sxo;
    int sy = h0 * area + 4 * itc;
    int xmn = occ  ? (w4 + __ffs(occ) - 1)             : (1 << 29);
    int xmx = occ  ? (w4 + 31 - __clz(occ))            : -1;
    int ymn = rocc ? (h0 + 4 * (__ffs(rocc) - 1))      : (1 << 29);
    int ymx = rocc ? (h0 + 4 * (31 - __clz(rocc)))     : -1;

    #pragma unroll
    for (int off = 16; off; off >>= 1) {
        area += __shfl_down_sync(0xffffffffu, area, off);
        sx   += __shfl_down_sync(0xffffffffu, sx, off);
        sy   += __shfl_down_sync(0xffffffffu, sy, off);
        xmn = min(xmn, __shfl_down_sync(0xffffffffu, xmn, off));
        xmx = max(xmx, __shfl_down_sync(0xffffffffu, xmx, off));
        ymn = min(ymn, __shfl_down_sync(0xffffffffu, ymn, off));
        ymx = max(ymx, __shfl_down_sync(0xffffffffu, ymx, off));
    }
    __shared__ int sA[15], sX[15], sY[15], sxm[15], sxM[15], sym[15], syM[15];
    const int wid = tid >> 5, lid = tid & 31;
    if (lid == 0) {
        sA[wid] = area; sX[wid] = sx; sY[wid] = sy;
        sxm[wid] = xmn; sxM[wid] = xmx; sym[wid] = ymn; syM[wid] = ymx;
    }
    __syncthreads();
    if (tid == 0) {
        int A = 0, X = 0, Y = 0, xm = 1 << 29, xM = -1, ym = 1 << 29, yM = -1;
        #pragma unroll
        for (int i = 0; i < 15; i++) {
            A += sA[i]; X += sX[i]; Y += sY[i];
            xm = min(xm, sxm[i]); xM = max(xM, sxM[i]);
            ym = min(ym, sym[i]); yM = max(yM, syM[i]);
        }
        int* st = g_stat4[chunk][bk];
        st[0] = A; st[1] = X; st[2] = Y;
        st[3] = xm; st[4] = xM; st[5] = ym; st[6] = yM;
    }
}

// ============================================================
// Kernel 2: masked pooling via SMEM-staged fm tiles + 0/1 multipliers.
// grid = (4 d-chunks, 4 k-groups of 8, 8 b), 256 threads.
// ============================================================
__global__ __launch_bounds__(256) void k_pool(const float* __restrict__ fm) {
    const int dc  = blockIdx.x;
    const int kg  = blockIdx.y;
    const int b   = blockIdx.z;
    const int tid = threadIdx.x;
    const int d   = dc * 256 + tid;
    const int k0  = kg * 8;

    __shared__ alignas(16) float4 s_m[Nn][2];
    __shared__ alignas(16) float  s_f[24][256];
    __shared__ float s_inv[8];

    for (int n = tid; n < Nn; n += 256) {
        float mk[8];
        #pragma unroll
        for (int kk = 0; kk < 8; kk++) {
            unsigned word = g_bits[(b * Kk + k0 + kk) * 18 + (n >> 5)];
            mk[kk] = ((word >> (n & 31)) & 1u) ? 1.0f : 0.0f;
        }
        s_m[n][0] = make_float4(mk[0], mk[1], mk[2], mk[3]);
        s_m[n][1] = make_float4(mk[4], mk[5], mk[6], mk[7]);
    }
    if (tid < 8) {
        int c = g_cnt[b * Kk + k0 + tid];
        s_inv[tid] = (c > 0) ? (1.0f / (float)c) : 0.0f;
    }
    __syncthreads();

    float a0 = 0.f, a1 = 0.f, a2 = 0.f, a3 = 0.f;
    float a4 = 0.f, a5 = 0.f, a6 = 0.f, a7 = 0.f;
    const float* fb = fm + (size_t)b * Nn * Dd;
    const int r4 = tid >> 6, c4 = tid & 63;

    for (int n0 = 0; n0 < Nn; n0 += 24) {
        const float4* src = reinterpret_cast<const float4*>(fb + (size_t)n0 * Dd) + dc * 64;
        float4* dst = reinterpret_cast<float4*>(s_f);
        #pragma unroll
        for (int p = 0; p < 6; p++) {
            int r = r4 + p * 4;
            dst[r * 64 + c4] = src[(size_t)r * 256 + c4];
        }
        __syncthreads();
        #pragma unroll 8
        for (int r2 = 0; r2 < 24; r2++) {
            float f = s_f[r2][tid];
            float4 m0 = s_m[n0 + r2][0];
            float4 m1 = s_m[n0 + r2][1];
            a0 = fmaf(f, m0.x, a0); a1 = fmaf(f, m0.y, a1);
            a2 = fmaf(f, m0.z, a2); a3 = fmaf(f, m0.w, a3);
            a4 = fmaf(f, m1.x, a4); a5 = fmaf(f, m1.y, a5);
            a6 = fmaf(f, m1.z, a6); a7 = fmaf(f, m1.w, a7);
        }
        __syncthreads();
    }

    float* pp = g_x + (size_t)(b * Kk + k0) * XS + d;
    pp[0 * XS] = a0 * s_inv[0];
    pp[1 * XS] = a1 * s_inv[1];
    pp[2 * XS] = a2 * s_inv[2];
    pp[3 * XS] = a3 * s_inv[3];
    pp[4 * XS] = a4 * s_inv[4];
    pp[5 * XS] = a5 * s_inv[5];
    pp[6 * XS] = a6 * s_inv[6];
    pp[7 * XS] = a7 * s_inv[7];
}

// ============================================================
// Shared body: layer1 partial GEMM for one (split, row-group of 8).
// Software-pipelined W1 loads; split 15 fills geometry inline from g_stat4.
// ============================================================
__device__ __forceinline__ void mlp1_body(const int split, const int rg,
                                          const float* __restrict__ W1) {
    const int j   = threadIdx.x;
    const int i0  = split * SLEN;
    const int len = min(SLEN, INDIM - i0);
    const int lim = min(len, GEOM_I - i0);   // exclude geom slots (computed inline)

    __shared__ alignas(16) float xs[8][SLEN + 3];

    #pragma unroll
    for (int r = 0; r < 8; r++) {
        if (j < lim) xs[r][j] = g_x[(size_t)(rg * 8 + r) * XS + i0 + j];
    }
    if (split == NSPLIT - 1 && j < 40) {
        const int r = j / 5, gsel = j - r * 5;
        const int bk = rg * 8 + r;
        int A = 0, SX = 0, SY = 0, xm = 1 << 29, xM = -1, ym = 1 << 29, yM = -1;
        #pragma unroll
        for (int c = 0; c < 4; c++) {
            const int* st = g_stat4[c][bk];
            A += st[0]; SX += st[1]; SY += st[2];
            xm = min(xm, st[3]); xM = max(xM, st[4]);
            ym = min(ym, st[5]); yM = max(yM, st[6]);
        }
        float af = (float)A, safe = fmaxf(af, 1.0f);
        float val;
        if      (gsel == 0) val = (float)SX / safe * (1.0f / Ww);
        else if (gsel == 1) val = (float)SY / safe * (1.0f / Hh);
        else if (gsel == 2) val = af * (1.0f / (Hh * Ww));
        else if (gsel == 3) val = (float)(xM - xm + 1) * (1.0f / Ww);
        else                val = (float)(yM - ym + 1) * (1.0f / Hh);
        xs[r][(GEOM_I - i0) + gsel] = (A >= 1) ? val : 0.0f;
    }
    __syncthreads();

    const float* wp = W1 + (size_t)i0 * OUTD + j;
    float a[8];
    #pragma unroll
    for (int r = 0; r < 8; r++) a[r] = 0.f;

    float w[8];
    #pragma unroll
    for (int u = 0; u < 8; u++) w[u] = wp[(size_t)u * OUTD];
    int t = 0;
    for (; t + 16 <= len; t += 8) {
        float wn[8];
        #pragma unroll
        for (int u = 0; u < 8; u++) wn[u] = wp[(size_t)(t + 8 + u) * OUTD];
        #pragma unroll
        for (int r = 0; r < 8; r++) {
            float4 xa = *(const float4*)&xs[r][t];
            float4 xb = *(const float4*)&xs[r][t + 4];
            a[r] = fmaf(xa.x, w[0], a[r]); a[r] = fmaf(xa.y, w[1], a[r]);
            a[r] = fmaf(xa.z, w[2], a[r]); a[r] = fmaf(xa.w, w[3], a[r]);
            a[r] = fmaf(xb.x, w[4], a[r]); a[r] = fmaf(xb.y, w[5], a[r]);
            a[r] = fmaf(xb.z, w[6], a[r]); a[r] = fmaf(xb.w, w[7], a[r]);
        }
        #pragma unroll
        for (int u = 0; u < 8; u++) w[u] = wn[u];
    }
    if (t + 8 <= len) {
        #pragma unroll
        for (int r = 0; r < 8; r++) {
            float4 xa = *(const float4*)&xs[r][t];
            float4 xb = *(const float4*)&xs[r][t + 4];
            a[r] = fmaf(xa.x, w[0], a[r]); a[r] = fmaf(xa.y, w[1], a[r]);
            a[r] = fmaf(xa.z, w[2], a[r]); a[r] = fmaf(xa.w, w[3], a[r]);
            a[r] = fmaf(xb.x, w[4], a[r]); a[r] = fmaf(xb.y, w[5], a[r]);
            a[r] = fmaf(xb.z, w[6], a[r]); a[r] = fmaf(xb.w, w[7], a[r]);
        }
        t += 8;
    }
    for (; t < len; t++) {
        float ws = wp[(size_t)t * OUTD];
        #pragma unroll
        for (int r = 0; r < 8; r++) a[r] = fmaf(xs[r][t], ws, a[r]);
    }

    float* gp = g_part + (size_t)(split * BK + rg * 8) * OUTD + j;
    #pragma unroll
    for (int r = 0; r < 8; r++) gp[(size_t)r * OUTD] = a[r];
}

// splits 0..14: depends only on pool/init -> overlaps k_mask.
__global__ __launch_bounds__(256) void k_mlp1_main(const float* __restrict__ W1) {
    mlp1_body(blockIdx.x, blockIdx.y, W1);
}
// split 15 (cls tail + geom): depends on init + mask only.
__global__ __launch_bounds__(256) void k_mlp1_geo(const float* __restrict__ W1) {
    mlp1_body(NSPLIT - 1, blockIdx.x, W1);
}

// ============================================================
// Kernel 3b: combine 16 partials + bias + exact GELU + LayerNorm + layer2.
// grid = 256 blocks (1 row), 256 threads, pipelined W2, dual accumulators.
// ============================================================
__global__ __launch_bounds__(256) void k_mlp2(const float* __restrict__ b1,
                                              const float* __restrict__ ln_g,
                                              const float* __restrict__ ln_b,
                                              const float* __restrict__ W2,
                                              const float* __restrict__ b2,
                                              float* __restrict__ out) {
    const int row = blockIdx.x;
    const int j   = threadIdx.x;

    __shared__ alignas(16) float hn[OUTD];
    __shared__ float red[2][8];
    __shared__ float mu_s, is_s;

    float v = b1[j];
    #pragma unroll
    for (int s = 0; s < NSPLIT; s++)
        v += g_part[(size_t)(s * BK + row) * OUTD + j];
    v = 0.5f * v * (1.0f + erff(v * 0.7071067811865476f));

    float s1 = v, s2 = v * v;
    #pragma unroll
    for (int off = 16; off; off >>= 1) {
        s1 += __shfl_down_sync(0xffffffffu, s1, off);
        s2 += __shfl_down_sync(0xffffffffu, s2, off);
    }
    if ((j & 31) == 0) { red[0][j >> 5] = s1; red[1][j >> 5] = s2; }
    __syncthreads();
    if (j == 0) {
        float a = 0.f, b = 0.f;
        #pragma unroll
        for (int w = 0; w < 8; w++) { a += red[0][w]; b += red[1][w]; }
        float mu  = a * (1.0f / OUTD);
        float var = b * (1.0f / OUTD) - mu * mu;
        mu_s = mu;
        is_s = rsqrtf(var + 1e-5f);
    }
    __syncthreads();
    hn[j] = (v - mu_s) * is_s * ln_g[j] + ln_b[j];
    __syncthreads();

    const float* wp = W2 + j;
    float o0 = b2[j], o1 = 0.f;
    float w[8];
    #pragma unroll
    for (int u = 0; u < 8; u++) w[u] = wp[(size_t)u * OUTD];
    int t = 0;
    for (; t + 16 <= OUTD; t += 8) {
        float wn[8];
        #pragma unroll
        for (int u = 0; u < 8; u++) wn[u] = wp[(size_t)(t + 8 + u) * OUTD];
        float4 ha = *(const float4*)&hn[t];
        float4 hb = *(const float4*)&hn[t + 4];
        o0 = fmaf(ha.x, w[0], o0); o1 = fmaf(ha.y, w[1], o1);
        o0 = fmaf(ha.z, w[2], o0); o1 = fmaf(ha.w, w[3], o1);
        o0 = fmaf(hb.x, w[4], o0); o1 = fmaf(hb.y, w[5], o1);
        o0 = fmaf(hb.z, w[6], o0); o1 = fmaf(hb.w, w[7], o1);
        #pragma unroll
        for (int u = 0; u < 8; u++) w[u] = wn[u];
    }
    {
        float4 ha = *(const float4*)&hn[t];
        float4 hb = *(const float4*)&hn[t + 4];
        o0 = fmaf(ha.x, w[0], o0); o1 = fmaf(ha.y, w[1], o1);
        o0 = fmaf(ha.z, w[2], o0); o1 = fmaf(ha.w, w[3], o1);
        o0 = fmaf(hb.x, w[4], o0); o1 = fmaf(hb.y, w[5], o1);
        o0 = fmaf(hb.z, w[6], o0); o1 = fmaf(hb.w, w[7], o1);
    }
    out[(size_t)row * OUTD + j] = o0 + o1;
}

// ============================================================
extern "C" void kernel_launch(void* const* d_in, const int* in_sizes, int n_in,
                              void* d_out, int out_size) {
    const float* fm    = (const float*)d_in[0];
    const int*   masks = (const int*)d_in[1];
    const void*  cls   = d_in[2];
    const float* emb   = (const float*)d_in[3];
    const float* W1    = (const float*)d_in[4];
    const float* b1    = (const float*)d_in[5];
    const float* lg    = (const float*)d_in[6];
    const float* lb    = (const float*)d_in[7];
    const float* W2    = (const float*)d_in[8];
    const float* b2    = (const float*)d_in[9];
    float* out = (float*)d_out;

    // Fork-join: k_mask (DRAM-bound) on s1 overlaps init+pool+mlp1_main.
    cudaStream_t s1 = 0;
    cudaEvent_t  e0 = 0, e1 = 0;
    bool forked =
        (cudaStreamCreateWithFlags(&s1, cudaStreamNonBlocking) == cudaSuccess) &&
        (cudaEventCreateWithFlags(&e0, cudaEventDisableTiming) == cudaSuccess) &&
        (cudaEventCreateWithFlags(&e1, cudaEventDisableTiming) == cudaSuccess);

    if (forked) {
        cudaEventRecord(e0, 0);
        cudaStreamWaitEvent(s1, e0, 0);
        k_mask<<<dim3(4, BK), 480, 0, s1>>>(masks);
        cudaEventRecord(e1, s1);

        k_init<<<BK, 576>>>(masks, cls, emb);
        k_pool<<<dim3(4, 4, 8), 256>>>(fm);
        k_mlp1_main<<<dim3(NSPLIT - 1, 32), 256>>>(W1);   // splits 0..14

        cudaStreamWaitEvent(0, e1, 0);                    // join: geom needs mask
        k_mlp1_geo<<<32, 256>>>(W1);                      // split 15
        k_mlp2<<<BK, 256>>>(b1, lg, lb, W2, b2, out);
    } else {
        k_init<<<BK, 576>>>(masks, cls, emb);
        k_mask<<<dim3(4, BK), 480>>>(masks);
        k_pool<<<dim3(4, 4, 8), 256>>>(fm);
        k_mlp1_main<<<dim3(NSPLIT - 1, 32), 256>>>(W1);
        k_mlp1_geo<<<32, 256>>>(W1);
        k_mlp2<<<BK, 256>>>(b1, lg, lb, W2, b2, out);
    }

    if (e0) cudaEventDestroy(e0);
    if (e1) cudaEventDestroy(e1);
    if (s1) cudaStreamDestroy(s1);
}

// round 10
// speedup vs baseline: 1.7506x; 1.3693x over previous
#include <cuda_runtime.h>
#include <cuda_bf16.h>
#include <math.h>

#define Kk 32
#define Hh 480
#define Ww 480
#define Nn 576
#define Dd 1024
#define CLSD 64
#define OUTD 256
#define INDIM 1093
#define BK 256
#define XS 1096    // padded row stride of assembled x
#define NSPLIT 16
#define SLEN 69    // ceil(1093/16)
#define GEOM_I 1088  // Dd + CLSD
#define NCHUNK 15  // k_mask row-chunks (32 rows each)

// ---- scratch (static device globals: allocation-free) ----
__device__ int      g_stat15[NCHUNK][BK][8]; // per-chunk partial stats (no init needed)
__device__ unsigned g_bits[BK * 18];         // 576-bit sample mask per (b,k)
__device__ int      g_cnt[BK];
__device__ float    g_x[BK * XS];            // assembled [pooled | cls | (geom inline)]
__device__ float    g_part[NSPLIT * BK * OUTD];

// ============================================================
// Kernel 0: sample bits + class-embedding gather.
// grid = 256 (one per b,k), 576 threads (24x24 sample grid).
// ============================================================
__global__ __launch_bounds__(576) void k_init(const int* __restrict__ masks,
                                              const void* __restrict__ cls_raw,
                                              const float* __restrict__ emb) {
    const int bk  = blockIdx.x;
    const int tid = threadIdx.x;
    const int wid = tid >> 5, lid = tid & 31;
    __shared__ int s_flag, s_cnt;
    if (tid == 0) { s_flag = 0; s_cnt = 0; }
    __syncthreads();
    // detect int64 vs int32 class_ids (odd 32-bit words all zero => int64)
    if (tid < 128) {
        if (((const int*)cls_raw)[2 * tid + 1] != 0) atomicOr(&s_flag, 1);
    }
    // sampled 24x24 bits (nearest: src = 20*i, 20*j)
    const int* mb = masks + (size_t)bk * (Hh * Ww);
    int i = tid / 24, j = tid - i * 24;
    int on = mb[(20 * i) * Ww + 20 * j] > 0;
    unsigned bal = __ballot_sync(0xffffffffu, on);
    if (lid == 0) { g_bits[bk * 18 + wid] = bal; atomicAdd(&s_cnt, __popc(bal)); }
    __syncthreads();
    if (tid == 0) g_cnt[bk] = s_cnt;
    const bool is64 = (s_flag == 0);
    int c = is64 ? (int)((const long long*)cls_raw)[bk]
                 : ((const int*)cls_raw)[bk];
    if (tid < CLSD) g_x[(size_t)bk * XS + Dd + tid] = emb[c * CLSD + tid];
}

// ============================================================
// Kernel 1: full-res mask stats. ONE load-round per warp: 8 streaming
// LDG.128 per thread in a single batch, pure-ALU processing after.
// grid = (15 chunks of 32 rows, 256 bk) = 3840 blocks, 480 threads.
// ============================================================
__global__ __launch_bounds__(480) void k_mask(const int* __restrict__ masks) {
    const int chunk = blockIdx.x;          // 0..14 (32 rows each)
    const int bk    = blockIdx.y;
    const int tid   = threadIdx.x;
    const int col4  = tid % 120;
    const int rowg  = tid / 120;           // 0..3
    const int h0    = chunk * 32 + rowg;
    const int4* mp  = reinterpret_cast<const int4*>(masks + (size_t)bk * (Hh * Ww))
                      + (size_t)h0 * 120 + col4;

    // single 8-deep load batch (streaming: no L2 pollution, zero reuse)
    int4 v[8];
    #pragma unroll
    for (int t = 0; t < 8; t++)
        v[t] = __ldcs(&mp[(size_t)t * 480]);

    int area = 0, itc = 0, sxo = 0, occ = 0;
    unsigned rocc = 0;
    #pragma unroll
    for (int t = 0; t < 8; t++) {
        int c = v[t].x + v[t].y + v[t].z + v[t].w;
        area += c;
        itc  += c * t;
        sxo  += v[t].y + 2 * v[t].z + 3 * v[t].w;
        occ  |= v[t].x + 2 * v[t].y + 4 * v[t].z + 8 * v[t].w;
        rocc |= ((unsigned)(c + 3) >> 2) << t;      // 1 iff c>=1
    }
    const int w4 = col4 * 4;
    int sx = w4 * area + sxo;
    int sy = h0 * area + 4 * itc;
    int xmn = occ  ? (w4 + __ffs(occ) - 1)         : (1 << 29);
    int xmx = occ  ? (w4 + 31 - __clz(occ))        : -1;
    int ymn = rocc ? (h0 + 4 * (__ffs(rocc) - 1))  : (1 << 29);
    int ymx = rocc ? (h0 + 4 * (31 - __clz(rocc))) : -1;

    #pragma unroll
    for (int off = 16; off; off >>= 1) {
        area += __shfl_down_sync(0xffffffffu, area, off);
        sx   += __shfl_down_sync(0xffffffffu, sx, off);
        sy   += __shfl_down_sync(0xffffffffu, sy, off);
        xmn = min(xmn, __shfl_down_sync(0xffffffffu, xmn, off));
        xmx = max(xmx, __shfl_down_sync(0xffffffffu, xmx, off));
        ymn = min(ymn, __shfl_down_sync(0xffffffffu, ymn, off));
        ymx = max(ymx, __shfl_down_sync(0xffffffffu, ymx, off));
    }
    __shared__ int sA[15], sX[15], sY[15], sxm[15], sxM[15], sym[15], syM[15];
    const int wid = tid >> 5, lid = tid & 31;
    if (lid == 0) {
        sA[wid] = area; sX[wid] = sx; sY[wid] = sy;
        sxm[wid] = xmn; sxM[wid] = xmx; sym[wid] = ymn; syM[wid] = ymx;
    }
    __syncthreads();
    if (tid == 0) {
        int A = 0, X = 0, Y = 0, xm = 1 << 29, xM = -1, ym = 1 << 29, yM = -1;
        #pragma unroll
        for (int i = 0; i < 15; i++) {
            A += sA[i]; X += sX[i]; Y += sY[i];
            xm = min(xm, sxm[i]); xM = max(xM, sxM[i]);
            ym = min(ym, sym[i]); yM = max(yM, syM[i]);
        }
        int* st = g_stat15[chunk][bk];
        st[0] = A; st[1] = X; st[2] = Y;
        st[3] = xm; st[4] = xM; st[5] = ym; st[6] = yM;
    }
}

// ============================================================
// Kernel 2: masked pooling via SMEM-staged fm tiles + 0/1 multipliers.
// grid = (4 d-chunks, 4 k-groups of 8, 8 b), 256 threads.
// ============================================================
__global__ __launch_bounds__(256) void k_pool(const float* __restrict__ fm) {
    const int dc  = blockIdx.x;
    const int kg  = blockIdx.y;
    const int b   = blockIdx.z;
    const int tid = threadIdx.x;
    const int d   = dc * 256 + tid;
    const int k0  = kg * 8;

    __shared__ alignas(16) float4 s_m[Nn][2];
    __shared__ alignas(16) float  s_f[24][256];
    __shared__ float s_inv[8];

    for (int n = tid; n < Nn; n += 256) {
        float mk[8];
        #pragma unroll
        for (int kk = 0; kk < 8; kk++) {
            unsigned word = g_bits[(b * Kk + k0 + kk) * 18 + (n >> 5)];
            mk[kk] = ((word >> (n & 31)) & 1u) ? 1.0f : 0.0f;
        }
        s_m[n][0] = make_float4(mk[0], mk[1], mk[2], mk[3]);
        s_m[n][1] = make_float4(mk[4], mk[5], mk[6], mk[7]);
    }
    if (tid < 8) {
        int c = g_cnt[b * Kk + k0 + tid];
        s_inv[tid] = (c > 0) ? (1.0f / (float)c) : 0.0f;
    }
    __syncthreads();

    float a0 = 0.f, a1 = 0.f, a2 = 0.f, a3 = 0.f;
    float a4 = 0.f, a5 = 0.f, a6 = 0.f, a7 = 0.f;
    const float* fb = fm + (size_t)b * Nn * Dd;
    const int r4 = tid >> 6, c4 = tid & 63;

    for (int n0 = 0; n0 < Nn; n0 += 24) {
        const float4* src = reinterpret_cast<const float4*>(fb + (size_t)n0 * Dd) + dc * 64;
        float4* dst = reinterpret_cast<float4*>(s_f);
        #pragma unroll
        for (int p = 0; p < 6; p++) {
            int r = r4 + p * 4;
            dst[r * 64 + c4] = src[(size_t)r * 256 + c4];
        }
        __syncthreads();
        #pragma unroll 8
        for (int r2 = 0; r2 < 24; r2++) {
            float f = s_f[r2][tid];
            float4 m0 = s_m[n0 + r2][0];
            float4 m1 = s_m[n0 + r2][1];
            a0 = fmaf(f, m0.x, a0); a1 = fmaf(f, m0.y, a1);
            a2 = fmaf(f, m0.z, a2); a3 = fmaf(f, m0.w, a3);
            a4 = fmaf(f, m1.x, a4); a5 = fmaf(f, m1.y, a5);
            a6 = fmaf(f, m1.z, a6); a7 = fmaf(f, m1.w, a7);
        }
        __syncthreads();
    }

    float* pp = g_x + (size_t)(b * Kk + k0) * XS + d;
    pp[0 * XS] = a0 * s_inv[0];
    pp[1 * XS] = a1 * s_inv[1];
    pp[2 * XS] = a2 * s_inv[2];
    pp[3 * XS] = a3 * s_inv[3];
    pp[4 * XS] = a4 * s_inv[4];
    pp[5 * XS] = a5 * s_inv[5];
    pp[6 * XS] = a6 * s_inv[6];
    pp[7 * XS] = a7 * s_inv[7];
}

// ============================================================
// Shared body: layer1 partial GEMM for one (split, row-group of 8).
// Software-pipelined W1 loads; last split fills geometry inline from g_stat15.
// ============================================================
__device__ __forceinline__ void mlp1_body(const int split, const int rg,
                                          const float* __restrict__ W1) {
    const int j   = threadIdx.x;
    const int i0  = split * SLEN;
    const int len = min(SLEN, INDIM - i0);
    const int lim = min(len, GEOM_I - i0);   // exclude geom slots (computed inline)

    __shared__ alignas(16) float xs[8][SLEN + 3];

    #pragma unroll
    for (int r = 0; r < 8; r++) {
        if (j < lim) xs[r][j] = g_x[(size_t)(rg * 8 + r) * XS + i0 + j];
    }
    if (split == NSPLIT - 1 && j < 40) {
        const int r = j / 5, gsel = j - r * 5;
        const int bk = rg * 8 + r;
        int A = 0, SX = 0, SY = 0, xm = 1 << 29, xM = -1, ym = 1 << 29, yM = -1;
        #pragma unroll
        for (int c = 0; c < NCHUNK; c++) {
            const int* st = g_stat15[c][bk];
            A += st[0]; SX += st[1]; SY += st[2];
            xm = min(xm, st[3]); xM = max(xM, st[4]);
            ym = min(ym, st[5]); yM = max(yM, st[6]);
        }
        float af = (float)A, safe = fmaxf(af, 1.0f);
        float val;
        if      (gsel == 0) val = (float)SX / safe * (1.0f / Ww);
        else if (gsel == 1) val = (float)SY / safe * (1.0f / Hh);
        else if (gsel == 2) val = af * (1.0f / (Hh * Ww));
        else if (gsel == 3) val = (float)(xM - xm + 1) * (1.0f / Ww);
        else                val = (float)(yM - ym + 1) * (1.0f / Hh);
        xs[r][(GEOM_I - i0) + gsel] = (A >= 1) ? val : 0.0f;
    }
    __syncthreads();

    const float* wp = W1 + (size_t)i0 * OUTD + j;
    float a[8];
    #pragma unroll
    for (int r = 0; r < 8; r++) a[r] = 0.f;

    float w[8];
    #pragma unroll
    for (int u = 0; u < 8; u++) w[u] = wp[(size_t)u * OUTD];
    int t = 0;
    for (; t + 16 <= len; t += 8) {
        float wn[8];
        #pragma unroll
        for (int u = 0; u < 8; u++) wn[u] = wp[(size_t)(t + 8 + u) * OUTD];
        #pragma unroll
        for (int r = 0; r < 8; r++) {
            float4 xa = *(const float4*)&xs[r][t];
            float4 xb = *(const float4*)&xs[r][t + 4];
            a[r] = fmaf(xa.x, w[0], a[r]); a[r] = fmaf(xa.y, w[1], a[r]);
            a[r] = fmaf(xa.z, w[2], a[r]); a[r] = fmaf(xa.w, w[3], a[r]);
            a[r] = fmaf(xb.x, w[4], a[r]); a[r] = fmaf(xb.y, w[5], a[r]);
            a[r] = fmaf(xb.z, w[6], a[r]); a[r] = fmaf(xb.w, w[7], a[r]);
        }
        #pragma unroll
        for (int u = 0; u < 8; u++) w[u] = wn[u];
    }
    if (t + 8 <= len) {
        #pragma unroll
        for (int r = 0; r < 8; r++) {
            float4 xa = *(const float4*)&xs[r][t];
            float4 xb = *(const float4*)&xs[r][t + 4];
            a[r] = fmaf(xa.x, w[0], a[r]); a[r] = fmaf(xa.y, w[1], a[r]);
            a[r] = fmaf(xa.z, w[2], a[r]); a[r] = fmaf(xa.w, w[3], a[r]);
            a[r] = fmaf(xb.x, w[4], a[r]); a[r] = fmaf(xb.y, w[5], a[r]);
            a[r] = fmaf(xb.z, w[6], a[r]); a[r] = fmaf(xb.w, w[7], a[r]);
        }
        t += 8;
    }
    for (; t < len; t++) {
        float ws = wp[(size_t)t * OUTD];
        #pragma unroll
        for (int r = 0; r < 8; r++) a[r] = fmaf(xs[r][t], ws, a[r]);
    }

    float* gp = g_part + (size_t)(split * BK + rg * 8) * OUTD + j;
    #pragma unroll
    for (int r = 0; r < 8; r++) gp[(size_t)r * OUTD] = a[r];
}

// splits 0..14: depends only on pool/init -> overlaps k_mask.
__global__ __launch_bounds__(256) void k_mlp1_main(const float* __restrict__ W1) {
    mlp1_body(blockIdx.x, blockIdx.y, W1);
}
// split 15 (cls tail + geom): depends on init + mask only.
__global__ __launch_bounds__(256) void k_mlp1_geo(const float* __restrict__ W1) {
    mlp1_body(NSPLIT - 1, blockIdx.x, W1);
}

// ============================================================
// Kernel 3b: combine 16 partials + bias + exact GELU + LayerNorm + layer2.
// grid = 256 blocks (1 row), 256 threads, pipelined W2, dual accumulators.
// ============================================================
__global__ __launch_bounds__(256) void k_mlp2(const float* __restrict__ b1,
                                              const float* __restrict__ ln_g,
                                              const float* __restrict__ ln_b,
                                              const float* __restrict__ W2,
                                              const float* __restrict__ b2,
                                              float* __restrict__ out) {
    const int row = blockIdx.x;
    const int j   = threadIdx.x;

    __shared__ alignas(16) float hn[OUTD];
    __shared__ float red[2][8];
    __shared__ float mu_s, is_s;

    float v = b1[j];
    #pragma unroll
    for (int s = 0; s < NSPLIT; s++)
        v += g_part[(size_t)(s * BK + row) * OUTD + j];
    v = 0.5f * v * (1.0f + erff(v * 0.7071067811865476f));

    float s1 = v, s2 = v * v;
    #pragma unroll
    for (int off = 16; off; off >>= 1) {
        s1 += __shfl_down_sync(0xffffffffu, s1, off);
        s2 += __shfl_down_sync(0xffffffffu, s2, off);
    }
    if ((j & 31) == 0) { red[0][j >> 5] = s1; red[1][j >> 5] = s2; }
    __syncthreads();
    if (j == 0) {
        float a = 0.f, b = 0.f;
        #pragma unroll
        for (int w = 0; w < 8; w++) { a += red[0][w]; b += red[1][w]; }
        float mu  = a * (1.0f / OUTD);
        float var = b * (1.0f / OUTD) - mu * mu;
        mu_s = mu;
        is_s = rsqrtf(var + 1e-5f);
    }
    __syncthreads();
    hn[j] = (v - mu_s) * is_s * ln_g[j] + ln_b[j];
    __syncthreads();

    const float* wp = W2 + j;
    float o0 = b2[j], o1 = 0.f;
    float w[8];
    #pragma unroll
    for (int u = 0; u < 8; u++) w[u] = wp[(size_t)u * OUTD];
    int t = 0;
    for (; t + 16 <= OUTD; t += 8) {
        float wn[8];
        #pragma unroll
        for (int u = 0; u < 8; u++) wn[u] = wp[(size_t)(t + 8 + u) * OUTD];
        float4 ha = *(const float4*)&hn[t];
        float4 hb = *(const float4*)&hn[t + 4];
        o0 = fmaf(ha.x, w[0], o0); o1 = fmaf(ha.y, w[1], o1);
        o0 = fmaf(ha.z, w[2], o0); o1 = fmaf(ha.w, w[3], o1);
        o0 = fmaf(hb.x, w[4], o0); o1 = fmaf(hb.y, w[5], o1);
        o0 = fmaf(hb.z, w[6], o0); o1 = fmaf(hb.w, w[7], o1);
        #pragma unroll
        for (int u = 0; u < 8; u++) w[u] = wn[u];
    }
    {
        float4 ha = *(const float4*)&hn[t];
        float4 hb = *(const float4*)&hn[t + 4];
        o0 = fmaf(ha.x, w[0], o0); o1 = fmaf(ha.y, w[1], o1);
        o0 = fmaf(ha.z, w[2], o0); o1 = fmaf(ha.w, w[3], o1);
        o0 = fmaf(hb.x, w[4], o0); o1 = fmaf(hb.y, w[5], o1);
        o0 = fmaf(hb.z, w[6], o0); o1 = fmaf(hb.w, w[7], o1);
    }
    out[(size_t)row * OUTD + j] = o0 + o1;
}

// ============================================================
extern "C" void kernel_launch(void* const* d_in, const int* in_sizes, int n_in,
                              void* d_out, int out_size) {
    const float* fm    = (const float*)d_in[0];
    const int*   masks = (const int*)d_in[1];
    const void*  cls   = d_in[2];
    const float* emb   = (const float*)d_in[3];
    const float* W1    = (const float*)d_in[4];
    const float* b1    = (const float*)d_in[5];
    const float* lg    = (const float*)d_in[6];
    const float* lb    = (const float*)d_in[7];
    const float* W2    = (const float*)d_in[8];
    const float* b2    = (const float*)d_in[9];
    float* out = (float*)d_out;

    // Fork-join: k_mask (DRAM-bound) on s1 overlaps init+pool+mlp1_main.
    cudaStream_t s1 = 0;
    cudaEvent_t  e0 = 0, e1 = 0;
    bool forked =
        (cudaStreamCreateWithFlags(&s1, cudaStreamNonBlocking) == cudaSuccess) &&
        (cudaEventCreateWithFlags(&e0, cudaEventDisableTiming) == cudaSuccess) &&
        (cudaEventCreateWithFlags(&e1, cudaEventDisableTiming) == cudaSuccess);

    if (forked) {
        cudaEventRecord(e0, 0);
        cudaStreamWaitEvent(s1, e0, 0);
        k_mask<<<dim3(NCHUNK, BK), 480, 0, s1>>>(masks);
        cudaEventRecord(e1, s1);

        k_init<<<BK, 576>>>(masks, cls, emb);
        k_pool<<<dim3(4, 4, 8), 256>>>(fm);
        k_mlp1_main<<<dim3(NSPLIT - 1, 32), 256>>>(W1);   // splits 0..14

        cudaStreamWaitEvent(0, e1, 0);                    // join: geom needs mask
        k_mlp1_geo<<<32, 256>>>(W1);                      // split 15
        k_mlp2<<<BK, 256>>>(b1, lg, lb, W2, b2, out);
    } else {
        k_init<<<BK, 576>>>(masks, cls, emb);
        k_mask<<<dim3(NCHUNK, BK), 480>>>(masks);
        k_pool<<<dim3(4, 4, 8), 256>>>(fm);
        k_mlp1_main<<<dim3(NSPLIT - 1, 32), 256>>>(W1);
        k_mlp1_geo<<<32, 256>>>(W1);
        k_mlp2<<<BK, 256>>>(b1, lg, lb, W2, b2, out);
    }

    if (e0) cudaEventDestroy(e0);
    if (e1) cudaEventDestroy(e1);
    if (s1) cudaStreamDestroy(s1);
}

// round 11
// speedup vs baseline: 1.8588x; 1.0619x over previous
#include <cuda_runtime.h>
#include <cuda_bf16.h>
#include <math.h>

#define Kk 32
#define Hh 480
#define Ww 480
#define Nn 576
#define Dd 1024
#define CLSD 64
#define OUTD 256
#define INDIM 1093
#define BK 256
#define XS 1096      // padded row stride of assembled x
#define NSPLIT 16
#define SLEN 68      // 16*68 = 1088 = Dd+CLSD exactly; geom handled in mlp2
#define GEOM_I 1088  // Dd + CLSD
#define NCHUNK 15    // k_mask row-chunks (32 rows each)

// ---- scratch (static device globals: allocation-free) ----
__device__ int      g_stat15[NCHUNK][BK][8]; // per-chunk partial stats (no init needed)
__device__ unsigned g_bits[BK * 18];         // 576-bit sample mask per (b,k)
__device__ int      g_cnt[BK];
__device__ float    g_x[BK * XS];            // assembled [pooled | cls]
__device__ float    g_part[NSPLIT * BK * OUTD];

// ============================================================
// Kernel 0: sample bits + class-embedding gather.
// grid = 256 (one per b,k), 576 threads (24x24 sample grid).
// ============================================================
__global__ __launch_bounds__(576) void k_init(const int* __restrict__ masks,
                                              const void* __restrict__ cls_raw,
                                              const float* __restrict__ emb) {
    const int bk  = blockIdx.x;
    const int tid = threadIdx.x;
    const int wid = tid >> 5, lid = tid & 31;
    __shared__ int s_flag, s_cnt;
    if (tid == 0) { s_flag = 0; s_cnt = 0; }
    __syncthreads();
    // detect int64 vs int32 class_ids (odd 32-bit words all zero => int64)
    if (tid < 128) {
        if (((const int*)cls_raw)[2 * tid + 1] != 0) atomicOr(&s_flag, 1);
    }
    // sampled 24x24 bits (nearest: src = 20*i, 20*j)
    const int* mb = masks + (size_t)bk * (Hh * Ww);
    int i = tid / 24, j = tid - i * 24;
    int on = mb[(20 * i) * Ww + 20 * j] > 0;
    unsigned bal = __ballot_sync(0xffffffffu, on);
    if (lid == 0) { g_bits[bk * 18 + wid] = bal; atomicAdd(&s_cnt, __popc(bal)); }
    __syncthreads();
    if (tid == 0) g_cnt[bk] = s_cnt;
    const bool is64 = (s_flag == 0);
    int c = is64 ? (int)((const long long*)cls_raw)[bk]
                 : ((const int*)cls_raw)[bk];
    if (tid < CLSD) g_x[(size_t)bk * XS + Dd + tid] = emb[c * CLSD + tid];
}

// ============================================================
// Kernel 1: full-res mask stats. ONE load-round per warp: 8 streaming
// LDG.128/thread in a single batch; parallel 7-thread final reduce.
// grid = (15 chunks of 32 rows, 256 bk) = 3840 blocks, 480 threads.
// ============================================================
__global__ __launch_bounds__(480) void k_mask(const int* __restrict__ masks) {
    const int chunk = blockIdx.x;          // 0..14 (32 rows each)
    const int bk    = blockIdx.y;
    const int tid   = threadIdx.x;
    const int col4  = tid % 120;
    const int rowg  = tid / 120;           // 0..3
    const int h0    = chunk * 32 + rowg;
    const int4* mp  = reinterpret_cast<const int4*>(masks + (size_t)bk * (Hh * Ww))
                      + (size_t)h0 * 120 + col4;

    // single 8-deep load batch (streaming: no L2 pollution, zero reuse)
    int4 v[8];
    #pragma unroll
    for (int t = 0; t < 8; t++)
        v[t] = __ldcs(&mp[(size_t)t * 480]);

    int area = 0, itc = 0, sxo = 0, occ = 0;
    unsigned rocc = 0;
    #pragma unroll
    for (int t = 0; t < 8; t++) {
        int c = v[t].x + v[t].y + v[t].z + v[t].w;
        area += c;
        itc  += c * t;
        sxo  += v[t].y + 2 * v[t].z + 3 * v[t].w;
        occ  |= v[t].x + 2 * v[t].y + 4 * v[t].z + 8 * v[t].w;
        rocc |= ((unsigned)(c + 3) >> 2) << t;      // 1 iff c>=1
    }
    const int w4 = col4 * 4;
    int sx = w4 * area + sxo;
    int sy = h0 * area + 4 * itc;
    int xmn = occ  ? (w4 + __ffs(occ) - 1)         : (1 << 29);
    int xmx = occ  ? (w4 + 31 - __clz(occ))        : -1;
    int ymn = rocc ? (h0 + 4 * (__ffs(rocc) - 1))  : (1 << 29);
    int ymx = rocc ? (h0 + 4 * (31 - __clz(rocc))) : -1;

    #pragma unroll
    for (int off = 16; off; off >>= 1) {
        area += __shfl_down_sync(0xffffffffu, area, off);
        sx   += __shfl_down_sync(0xffffffffu, sx, off);
        sy   += __shfl_down_sync(0xffffffffu, sy, off);
        xmn = min(xmn, __shfl_down_sync(0xffffffffu, xmn, off));
        xmx = max(xmx, __shfl_down_sync(0xffffffffu, xmx, off));
        ymn = min(ymn, __shfl_down_sync(0xffffffffu, ymn, off));
        ymx = max(ymx, __shfl_down_sync(0xffffffffu, ymx, off));
    }
    __shared__ int red7[15][8];
    const int wid = tid >> 5, lid = tid & 31;
    if (lid == 0) {
        int* r = red7[wid];
        r[0] = area; r[1] = sx; r[2] = sy;
        r[3] = xmn; r[4] = xmx; r[5] = ymn; r[6] = ymx;
    }
    __syncthreads();
    // parallel final reduce: one thread per statistic (15 batched LDS each)
    if (tid < 7) {
        int acc = red7[0][tid];
        if (tid < 3) {                 // sums
            #pragma unroll
            for (int i = 1; i < 15; i++) acc += red7[i][tid];
        } else if (tid == 3 || tid == 5) {  // mins
            #pragma unroll
            for (int i = 1; i < 15; i++) acc = min(acc, red7[i][tid]);
        } else {                       // maxs
            #pragma unroll
            for (int i = 1; i < 15; i++) acc = max(acc, red7[i][tid]);
        }
        g_stat15[chunk][bk][tid] = acc;
    }
}

// ============================================================
// Kernel 2: masked pooling via SMEM-staged fm tiles + 0/1 multipliers.
// grid = (4 d-chunks, 4 k-groups of 8, 8 b), 256 threads.
// ============================================================
__global__ __launch_bounds__(256) void k_pool(const float* __restrict__ fm) {
    const int dc  = blockIdx.x;
    const int kg  = blockIdx.y;
    const int b   = blockIdx.z;
    const int tid = threadIdx.x;
    const int d   = dc * 256 + tid;
    const int k0  = kg * 8;

    __shared__ alignas(16) float4 s_m[Nn][2];
    __shared__ alignas(16) float  s_f[24][256];
    __shared__ float s_inv[8];

    for (int n = tid; n < Nn; n += 256) {
        float mk[8];
        #pragma unroll
        for (int kk = 0; kk < 8; kk++) {
            unsigned word = g_bits[(b * Kk + k0 + kk) * 18 + (n >> 5)];
            mk[kk] = ((word >> (n & 31)) & 1u) ? 1.0f : 0.0f;
        }
        s_m[n][0] = make_float4(mk[0], mk[1], mk[2], mk[3]);
        s_m[n][1] = make_float4(mk[4], mk[5], mk[6], mk[7]);
    }
    if (tid < 8) {
        int c = g_cnt[b * Kk + k0 + tid];
        s_inv[tid] = (c > 0) ? (1.0f / (float)c) : 0.0f;
    }
    __syncthreads();

    float a0 = 0.f, a1 = 0.f, a2 = 0.f, a3 = 0.f;
    float a4 = 0.f, a5 = 0.f, a6 = 0.f, a7 = 0.f;
    const float* fb = fm + (size_t)b * Nn * Dd;
    const int r4 = tid >> 6, c4 = tid & 63;

    for (int n0 = 0; n0 < Nn; n0 += 24) {
        const float4* src = reinterpret_cast<const float4*>(fb + (size_t)n0 * Dd) + dc * 64;
        float4* dst = reinterpret_cast<float4*>(s_f);
        #pragma unroll
        for (int p = 0; p < 6; p++) {
            int r = r4 + p * 4;
            dst[r * 64 + c4] = src[(size_t)r * 256 + c4];
        }
        __syncthreads();
        #pragma unroll 8
        for (int r2 = 0; r2 < 24; r2++) {
            float f = s_f[r2][tid];
            float4 m0 = s_m[n0 + r2][0];
            float4 m1 = s_m[n0 + r2][1];
            a0 = fmaf(f, m0.x, a0); a1 = fmaf(f, m0.y, a1);
            a2 = fmaf(f, m0.z, a2); a3 = fmaf(f, m0.w, a3);
            a4 = fmaf(f, m1.x, a4); a5 = fmaf(f, m1.y, a5);
            a6 = fmaf(f, m1.z, a6); a7 = fmaf(f, m1.w, a7);
        }
        __syncthreads();
    }

    float* pp = g_x + (size_t)(b * Kk + k0) * XS + d;
    pp[0 * XS] = a0 * s_inv[0];
    pp[1 * XS] = a1 * s_inv[1];
    pp[2 * XS] = a2 * s_inv[2];
    pp[3 * XS] = a3 * s_inv[3];
    pp[4 * XS] = a4 * s_inv[4];
    pp[5 * XS] = a5 * s_inv[5];
    pp[6 * XS] = a6 * s_inv[6];
    pp[7 * XS] = a7 * s_inv[7];
}

// ============================================================
// Kernel 3a: layer1 partial GEMM over i=0..1087 (pooled+cls only).
// grid = (16 splits of 68, 32 row-groups of 8) = 512 blocks, 256 threads.
// Entirely pre-join: depends only on k_init + k_pool.
// ============================================================
__global__ __launch_bounds__(256) void k_mlp1(const float* __restrict__ W1) {
    const int split = blockIdx.x;
    const int rg    = blockIdx.y;
    const int j     = threadIdx.x;
    const int i0    = split * SLEN;

    __shared__ alignas(16) float xs[8][SLEN + 4];

    #pragma unroll
    for (int r = 0; r < 8; r++) {
        if (j < SLEN) xs[r][j] = g_x[(size_t)(rg * 8 + r) * XS + i0 + j];
    }
    __syncthreads();

    const float* wp = W1 + (size_t)i0 * OUTD + j;
    float a[8];
    #pragma unroll
    for (int r = 0; r < 8; r++) a[r] = 0.f;

    float w[8];
    #pragma unroll
    for (int u = 0; u < 8; u++) w[u] = wp[(size_t)u * OUTD];
    int t = 0;
    for (; t + 16 <= SLEN; t += 8) {
        float wn[8];
        #pragma unroll
        for (int u = 0; u < 8; u++) wn[u] = wp[(size_t)(t + 8 + u) * OUTD];
        #pragma unroll
        for (int r = 0; r < 8; r++) {
            float4 xa = *(const float4*)&xs[r][t];
            float4 xb = *(const float4*)&xs[r][t + 4];
            a[r] = fmaf(xa.x, w[0], a[r]); a[r] = fmaf(xa.y, w[1], a[r]);
            a[r] = fmaf(xa.z, w[2], a[r]); a[r] = fmaf(xa.w, w[3], a[r]);
            a[r] = fmaf(xb.x, w[4], a[r]); a[r] = fmaf(xb.y, w[5], a[r]);
            a[r] = fmaf(xb.z, w[6], a[r]); a[r] = fmaf(xb.w, w[7], a[r]);
        }
        #pragma unroll
        for (int u = 0; u < 8; u++) w[u] = wn[u];
    }
    // SLEN = 68: main loop handled t=0..55 (8-blocks to 56..63 prefetched);
    // finish t=56..63 with registers, then scalar tail 64..67.
    {
        #pragma unroll
        for (int r = 0; r < 8; r++) {
            float4 xa = *(const float4*)&xs[r][t];
            float4 xb = *(const float4*)&xs[r][t + 4];
            a[r] = fmaf(xa.x, w[0], a[r]); a[r] = fmaf(xa.y, w[1], a[r]);
            a[r] = fmaf(xa.z, w[2], a[r]); a[r] = fmaf(xa.w, w[3], a[r]);
            a[r] = fmaf(xb.x, w[4], a[r]); a[r] = fmaf(xb.y, w[5], a[r]);
            a[r] = fmaf(xb.z, w[6], a[r]); a[r] = fmaf(xb.w, w[7], a[r]);
        }
        t += 8;
    }
    for (; t < SLEN; t++) {
        float ws = wp[(size_t)t * OUTD];
        #pragma unroll
        for (int r = 0; r < 8; r++) a[r] = fmaf(xs[r][t], ws, a[r]);
    }

    float* gp = g_part + (size_t)(split * BK + rg * 8) * OUTD + j;
    #pragma unroll
    for (int r = 0; r < 8; r++) gp[(size_t)r * OUTD] = a[r];
}

// ============================================================
// Kernel 3b: combine 16 partials + inline GEOMETRY contribution + bias +
// exact GELU + LayerNorm + layer2. grid = 256 blocks (1 row), 256 threads.
// Only post-join kernel.
// ============================================================
__global__ __launch_bounds__(256) void k_mlp2(const float* __restrict__ b1,
                                              const float* __restrict__ ln_g,
                                              const float* __restrict__ ln_b,
                                              const float* __restrict__ W1,
                                              const float* __restrict__ W2,
                                              const float* __restrict__ b2,
                                              float* __restrict__ out) {
    const int row = blockIdx.x;
    const int j   = threadIdx.x;

    __shared__ alignas(16) float hn[OUTD];
    __shared__ float s_geo[5];
    __shared__ float red[2][8];
    __shared__ float mu_s, is_s;

    // warp 0: reduce the 15 chunk-stat slots -> 5 geometry features
    if (j < 32) {
        int A = 0, SX = 0, SY = 0, xm = 1 << 29, xM = -1, ym = 1 << 29, yM = -1;
        if (j < NCHUNK) {
            const int* st = g_stat15[j][row];
            A = st[0]; SX = st[1]; SY = st[2];
            xm = st[3]; xM = st[4]; ym = st[5]; yM = st[6];
        }
        #pragma unroll
        for (int off = 8; off; off >>= 1) {
            A  += __shfl_down_sync(0xffffffffu, A, off);
            SX += __shfl_down_sync(0xffffffffu, SX, off);
            SY += __shfl_down_sync(0xffffffffu, SY, off);
            xm = min(xm, __shfl_down_sync(0xffffffffu, xm, off));
            xM = max(xM, __shfl_down_sync(0xffffffffu, xM, off));
            ym = min(ym, __shfl_down_sync(0xffffffffu, ym, off));
            yM = max(yM, __shfl_down_sync(0xffffffffu, yM, off));
        }
        if (j == 0) {
            float af = (float)A, safe = fmaxf(af, 1.0f);
            bool valid = (A >= 1);
            s_geo[0] = valid ? (float)SX / safe * (1.0f / Ww) : 0.0f;
            s_geo[1] = valid ? (float)SY / safe * (1.0f / Hh) : 0.0f;
            s_geo[2] = valid ? af * (1.0f / (Hh * Ww)) : 0.0f;
            s_geo[3] = valid ? (float)(xM - xm + 1) * (1.0f / Ww) : 0.0f;
            s_geo[4] = valid ? (float)(yM - ym + 1) * (1.0f / Hh) : 0.0f;
        }
    }

    float v = b1[j];
    #pragma unroll
    for (int s = 0; s < NSPLIT; s++)
        v += g_part[(size_t)(s * BK + row) * OUTD + j];
    __syncthreads();
    #pragma unroll
    for (int g = 0; g < 5; g++)
        v = fmaf(s_geo[g], W1[(size_t)(GEOM_I + g) * OUTD + j], v);
    v = 0.5f * v * (1.0f + erff(v * 0.7071067811865476f));

    float s1 = v, s2 = v * v;
    #pragma unroll
    for (int off = 16; off; off >>= 1) {
        s1 += __shfl_down_sync(0xffffffffu, s1, off);
        s2 += __shfl_down_sync(0xffffffffu, s2, off);
    }
    if ((j & 31) == 0) { red[0][j >> 5] = s1; red[1][j >> 5] = s2; }
    __syncthreads();
    if (j == 0) {
        float a = 0.f, b = 0.f;
        #pragma unroll
        for (int w = 0; w < 8; w++) { a += red[0][w]; b += red[1][w]; }
        float mu  = a * (1.0f / OUTD);
        float var = b * (1.0f / OUTD) - mu * mu;
        mu_s = mu;
        is_s = rsqrtf(var + 1e-5f);
    }
    __syncthreads();
    hn[j] = (v - mu_s) * is_s * ln_g[j] + ln_b[j];
    __syncthreads();

    const float* wp = W2 + j;
    float o0 = b2[j], o1 = 0.f;
    float w[8];
    #pragma unroll
    for (int u = 0; u < 8; u++) w[u] = wp[(size_t)u * OUTD];
    int t = 0;
    for (; t + 16 <= OUTD; t += 8) {
        float wn[8];
        #pragma unroll
        for (int u = 0; u < 8; u++) wn[u] = wp[(size_t)(t + 8 + u) * OUTD];
        float4 ha = *(const float4*)&hn[t];
        float4 hb = *(const float4*)&hn[t + 4];
        o0 = fmaf(ha.x, w[0], o0); o1 = fmaf(ha.y, w[1], o1);
        o0 = fmaf(ha.z, w[2], o0); o1 = fmaf(ha.w, w[3], o1);
        o0 = fmaf(hb.x, w[4], o0); o1 = fmaf(hb.y, w[5], o1);
        o0 = fmaf(hb.z, w[6], o0); o1 = fmaf(hb.w, w[7], o1);
        #pragma unroll
        for (int u = 0; u < 8; u++) w[u] = wn[u];
    }
    {
        float4 ha = *(const float4*)&hn[t];
        float4 hb = *(const float4*)&hn[t + 4];
        o0 = fmaf(ha.x, w[0], o0); o1 = fmaf(ha.y, w[1], o1);
        o0 = fmaf(ha.z, w[2], o0); o1 = fmaf(ha.w, w[3], o1);
        o0 = fmaf(hb.x, w[4], o0); o1 = fmaf(hb.y, w[5], o1);
        o0 = fmaf(hb.z, w[6], o0); o1 = fmaf(hb.w, w[7], o1);
    }
    out[(size_t)row * OUTD + j] = o0 + o1;
}

// ============================================================
extern "C" void kernel_launch(void* const* d_in, const int* in_sizes, int n_in,
                              void* d_out, int out_size) {
    const float* fm    = (const float*)d_in[0];
    const int*   masks = (const int*)d_in[1];
    const void*  cls   = d_in[2];
    const float* emb   = (const float*)d_in[3];
    const float* W1    = (const float*)d_in[4];
    const float* b1    = (const float*)d_in[5];
    const float* lg    = (const float*)d_in[6];
    const float* lb    = (const float*)d_in[7];
    const float* W2    = (const float*)d_in[8];
    const float* b2    = (const float*)d_in[9];
    float* out = (float*)d_out;

    // Fork-join: k_mask (DRAM-bound) on s1 overlaps init+pool+ALL of mlp1.
    cudaStream_t s1 = 0;
    cudaEvent_t  e0 = 0, e1 = 0;
    bool forked =
        (cudaStreamCreateWithFlags(&s1, cudaStreamNonBlocking) == cudaSuccess) &&
        (cudaEventCreateWithFlags(&e0, cudaEventDisableTiming) == cudaSuccess) &&
        (cudaEventCreateWithFlags(&e1, cudaEventDisableTiming) == cudaSuccess);

    if (forked) {
        cudaEventRecord(e0, 0);
        cudaStreamWaitEvent(s1, e0, 0);
        k_mask<<<dim3(NCHUNK, BK), 480, 0, s1>>>(masks);
        cudaEventRecord(e1, s1);

        k_init<<<BK, 576>>>(masks, cls, emb);
        k_pool<<<dim3(4, 4, 8), 256>>>(fm);
        k_mlp1<<<dim3(NSPLIT, 32), 256>>>(W1);

        cudaStreamWaitEvent(0, e1, 0);       // join: only mlp2 needs mask stats
        k_mlp2<<<BK, 256>>>(b1, lg, lb, W1, W2, b2, out);
    } else {
        k_init<<<BK, 576>>>(masks, cls, emb);
        k_mask<<<dim3(NCHUNK, BK), 480>>>(masks);
        k_pool<<<dim3(4, 4, 8), 256>>>(fm);
        k_mlp1<<<dim3(NSPLIT, 32), 256>>>(W1);
        k_mlp2<<<BK, 256>>>(b1, lg, lb, W1, W2, b2, out);
    }

    if (e0) cudaEventDestroy(e0);
    if (e1) cudaEventDestroy(e1);
    if (s1) cudaStreamDestroy(s1);
}